// round 9
// baseline (speedup 1.0000x reference)
#include <cuda_runtime.h>
#include <math.h>

#define N_ 32
#define O_ 2048
#define I_ 4096
#define I4_ (I_/4)          // 1024
#define E_ 3
#define D_ 8
#define H_ 16
#define SELF_W 0.7f
#define OB 4                // o-rows per work unit
#define NUNITS (O_ / OB)    // 512 og units per class
#define NCLASS 32           // i4-classes (32 columns each)

// Scratch (no allocs allowed)
__device__ float4 g_wnm4[N_ * I4_];   // w[n]*mask[n][i]/norm[i]
__device__ float4 g_a4[I4_];          // 0.7*tm[i]/norm[i]
__device__ int    g_ctr[NCLASS];      // per-class work counters

// ---------------------------------------------------------------------------
// Fused prologue: every block's warp 0 redundantly computes the 32 attention
// weights (concurrent across blocks), then all threads compute the
// per-column coefficients + bias output.  32 blocks x 128 threads.
// Block 0 also resets the work counters for the main kernel.
// ---------------------------------------------------------------------------
__global__ void __launch_bounds__(128)
prologue_kernel(const float* __restrict__ edge_feats,
                const float* __restrict__ node_feats,
                const float* __restrict__ W1e, const float* __restrict__ b1e,
                const float* __restrict__ W2e, const float* __restrict__ b2e,
                const float* __restrict__ W1n, const float* __restrict__ b1n,
                const float* __restrict__ W2n, const float* __restrict__ b2n,
                const float* __restrict__ target_b,
                const float* __restrict__ neighbor_b,
                const int*   __restrict__ target_mask,
                const int*   __restrict__ neighbor_masks,
                float* __restrict__ out_b)
{
    __shared__ float w_s[N_];
    const int tid = threadIdx.x;

    if (blockIdx.x == 0 && tid < NCLASS) g_ctr[tid] = 0;   // reset work queue

    if (tid < N_) {
        const int n = tid;
        float logit_e = b2e[0];
        #pragma unroll
        for (int h = 0; h < H_; h++) {
            float acc = b1e[h];
            #pragma unroll
            for (int e = 0; e < E_; e++)
                acc += edge_feats[n * E_ + e] * W1e[e * H_ + h];
            logit_e += tanhf(acc) * W2e[h];
        }
        const float score = 1.f / (1.f + expf(-logit_e));

        float logit_n = b2n[0];
        #pragma unroll
        for (int h = 0; h < H_; h++) {
            float acc = b1n[h];
            #pragma unroll
            for (int d = 0; d < D_; d++)
                acc += node_feats[n * D_ + d] * W1n[d * H_ + h];
            logit_n += tanhf(acc) * W2n[h];
        }
        const float cond = 1.f / (1.f + expf(-logit_n));

        const float s = score * cond;
        float m = s;
        #pragma unroll
        for (int off = 16; off; off >>= 1)
            m = fmaxf(m, __shfl_xor_sync(0xffffffffu, m, off));
        const float ex = expf(s - m);
        float sum = ex;
        #pragma unroll
        for (int off = 16; off; off >>= 1)
            sum += __shfl_xor_sync(0xffffffffu, sum, off);
        w_s[n] = (1.f - SELF_W) * ex / sum;
    }
    __syncthreads();

    float* g_wnm = (float*)g_wnm4;
    float* g_a   = (float*)g_a4;

    const int i = blockIdx.x * 128 + tid;          // [0, 4096)
    {
        const float tm = (float)target_mask[i];
        float wn[N_];
        float norm = 1e-8f + SELF_W * tm;
        #pragma unroll
        for (int n = 0; n < N_; n++) {
            wn[n] = w_s[n] * (float)neighbor_masks[n * I_ + i];
            norm += wn[n];
        }
        const float inv = 1.f / norm;
        g_a[i] = SELF_W * tm * inv;
        #pragma unroll
        for (int n = 0; n < N_; n++)
            g_wnm[n * I_ + i] = wn[n] * inv;
    }

    if (i < O_) {
        float acc = SELF_W * target_b[i];
        #pragma unroll
        for (int n = 0; n < N_; n++)
            acc += w_s[n] * neighbor_b[n * O_ + i];
        out_b[i] = acc;
    }
}

// ---------------------------------------------------------------------------
// Main: out_W[o,i] = target_W[o,i]*a[i] + sum_n wnm[n,i]*neighbor_W[n,o,i]
// Warp-level dynamic work distribution: each warp owns a fixed i4-class
// (lane i4 fixed -> coefficient loads cache-resident) and pulls og-units
// from a per-class atomic counter via lane0 atomicAdd + shfl.
// NO block barriers in the loop -> warps free-run, load issue stays smooth.
// 148 warps/class x 512 units -> near-perfect makespan balance.
// ---------------------------------------------------------------------------
#define MAIN_BLOCKS 592     // 148 SMs * 4 resident blocks
#define MAIN_THREADS 256

__global__ void __launch_bounds__(MAIN_THREADS)
main_kernel(const float4* __restrict__ tW,
            const float4* __restrict__ nW,
            float4* __restrict__ outW)
{
    cudaGridDependencySynchronize();

    const int wid   = threadIdx.x >> 5;
    const int lane  = threadIdx.x & 31;
    const int cls   = (blockIdx.x * 8 + wid) & (NCLASS - 1);
    const int i4    = cls * 32 + lane;                 // fixed per thread

    const float4 a = g_a4[i4];

    for (;;) {
        int og;
        if (lane == 0) og = atomicAdd(&g_ctr[cls], 1);
        og = __shfl_sync(0xffffffffu, og, 0);
        if (og >= NUNITS) break;

        const int o0 = og * OB;

        float4 acc[OB];
        #pragma unroll
        for (int oo = 0; oo < OB; oo++) {
            const float4 t = __ldcs(&tW[(size_t)(o0 + oo) * I4_ + i4]);
            acc[oo].x = t.x * a.x;
            acc[oo].y = t.y * a.y;
            acc[oo].z = t.z * a.z;
            acc[oo].w = t.w * a.w;
        }

        #pragma unroll 4
        for (int n = 0; n < N_; n++) {
            const float4 wv = g_wnm4[n * I4_ + i4];          // cache-resident
            const size_t base = (size_t)n * (O_ * I4_);
            #pragma unroll
            for (int oo = 0; oo < OB; oo++) {
                const float4 Wv = __ldcs(&nW[base + (size_t)(o0 + oo) * I4_ + i4]);
                acc[oo].x += wv.x * Wv.x;
                acc[oo].y += wv.y * Wv.y;
                acc[oo].z += wv.z * Wv.z;
                acc[oo].w += wv.w * Wv.w;
            }
        }

        #pragma unroll
        for (int oo = 0; oo < OB; oo++)
            __stcs(&outW[(size_t)(o0 + oo) * I4_ + i4], acc[oo]);
    }
}

// ---------------------------------------------------------------------------
extern "C" void kernel_launch(void* const* d_in, const int* in_sizes, int n_in,
                              void* d_out, int out_size)
{
    const float* edge_feats     = (const float*)d_in[0];
    const float* node_feats     = (const float*)d_in[1];
    const float* W1e            = (const float*)d_in[2];
    const float* b1e            = (const float*)d_in[3];
    const float* W2e            = (const float*)d_in[4];
    const float* b2e            = (const float*)d_in[5];
    const float* W1n            = (const float*)d_in[6];
    const float* b1n            = (const float*)d_in[7];
    const float* W2n            = (const float*)d_in[8];
    const float* b2n            = (const float*)d_in[9];
    const float* target_W       = (const float*)d_in[10];
    const float* neighbor_W     = (const float*)d_in[11];
    const float* target_b       = (const float*)d_in[12];
    const float* neighbor_b     = (const float*)d_in[13];
    const int*   target_mask    = (const int*)d_in[14];
    const int*   neighbor_masks = (const int*)d_in[15];

    float* out   = (float*)d_out;
    float* out_b = out + (size_t)O_ * I_;

    prologue_kernel<<<I_ / 128, 128>>>(edge_feats, node_feats,
                                       W1e, b1e, W2e, b2e,
                                       W1n, b1n, W2n, b2n,
                                       target_b, neighbor_b,
                                       target_mask, neighbor_masks,
                                       out_b);

    // PDL: main blocks scheduled while the prologue runs; gridDepSync inside
    // gates reads of g_a4/g_wnm4/g_ctr (counter reset happens-before).
    {
        cudaLaunchConfig_t cfg = {};
        cfg.gridDim  = dim3(MAIN_BLOCKS, 1, 1);
        cfg.blockDim = dim3(MAIN_THREADS, 1, 1);
        cfg.dynamicSmemBytes = 0;
        cfg.stream = 0;

        cudaLaunchAttribute attrs[1];
        attrs[0].id = cudaLaunchAttributeProgrammaticStreamSerialization;
        attrs[0].val.programmaticStreamSerializationAllowed = 1;
        cfg.attrs = attrs;
        cfg.numAttrs = 1;

        cudaLaunchKernelEx(&cfg, main_kernel,
                           (const float4*)target_W,
                           (const float4*)neighbor_W,
                           (float4*)out);
    }
}

// round 10
// speedup vs baseline: 1.0729x; 1.0729x over previous
#include <cuda_runtime.h>
#include <math.h>

#define N_ 32
#define O_ 2048
#define I_ 4096
#define I4_ (I_/4)          // 1024
#define E_ 3
#define D_ 8
#define H_ 16
#define SELF_W 0.7f
#define OB 2                // o-rows per iteration (finer static balance: 7/6 vs 4/3)

// Scratch (no allocs allowed)
__device__ float4 g_wnm4[N_ * I4_];   // w[n]*mask[n][i]/norm[i]
__device__ float4 g_a4[I4_];          // 0.7*tm[i]/norm[i]

// ---------------------------------------------------------------------------
// Fused prologue: every block's warp 0 redundantly computes the 32 attention
// weights (concurrent across blocks), then all threads compute the
// per-column coefficients + bias output.  32 blocks x 128 threads.
// ---------------------------------------------------------------------------
__global__ void __launch_bounds__(128)
prologue_kernel(const float* __restrict__ edge_feats,
                const float* __restrict__ node_feats,
                const float* __restrict__ W1e, const float* __restrict__ b1e,
                const float* __restrict__ W2e, const float* __restrict__ b2e,
                const float* __restrict__ W1n, const float* __restrict__ b1n,
                const float* __restrict__ W2n, const float* __restrict__ b2n,
                const float* __restrict__ target_b,
                const float* __restrict__ neighbor_b,
                const int*   __restrict__ target_mask,
                const int*   __restrict__ neighbor_masks,
                float* __restrict__ out_b)
{
    __shared__ float w_s[N_];
    const int tid = threadIdx.x;

    if (tid < N_) {
        const int n = tid;
        float logit_e = b2e[0];
        #pragma unroll
        for (int h = 0; h < H_; h++) {
            float acc = b1e[h];
            #pragma unroll
            for (int e = 0; e < E_; e++)
                acc += edge_feats[n * E_ + e] * W1e[e * H_ + h];
            logit_e += tanhf(acc) * W2e[h];
        }
        const float score = 1.f / (1.f + expf(-logit_e));

        float logit_n = b2n[0];
        #pragma unroll
        for (int h = 0; h < H_; h++) {
            float acc = b1n[h];
            #pragma unroll
            for (int d = 0; d < D_; d++)
                acc += node_feats[n * D_ + d] * W1n[d * H_ + h];
            logit_n += tanhf(acc) * W2n[h];
        }
        const float cond = 1.f / (1.f + expf(-logit_n));

        const float s = score * cond;
        float m = s;
        #pragma unroll
        for (int off = 16; off; off >>= 1)
            m = fmaxf(m, __shfl_xor_sync(0xffffffffu, m, off));
        const float ex = expf(s - m);
        float sum = ex;
        #pragma unroll
        for (int off = 16; off; off >>= 1)
            sum += __shfl_xor_sync(0xffffffffu, sum, off);
        w_s[n] = (1.f - SELF_W) * ex / sum;
    }
    __syncthreads();

    float* g_wnm = (float*)g_wnm4;
    float* g_a   = (float*)g_a4;

    const int i = blockIdx.x * 128 + tid;          // [0, 4096)
    {
        const float tm = (float)target_mask[i];
        float wn[N_];
        float norm = 1e-8f + SELF_W * tm;
        #pragma unroll
        for (int n = 0; n < N_; n++) {
            wn[n] = w_s[n] * (float)neighbor_masks[n * I_ + i];
            norm += wn[n];
        }
        const float inv = 1.f / norm;
        g_a[i] = SELF_W * tm * inv;
        #pragma unroll
        for (int n = 0; n < N_; n++)
            g_wnm[n * I_ + i] = wn[n] * inv;
    }

    if (i < O_) {
        float acc = SELF_W * target_b[i];
        #pragma unroll
        for (int n = 0; n < N_; n++)
            acc += w_s[n] * neighbor_b[n * O_ + i];
        out_b[i] = acc;
    }
}

// ---------------------------------------------------------------------------
// Main: out_W[o,i] = target_W[o,i]*a[i] + sum_n wnm[n,i]*neighbor_W[n,o,i]
// R7 static persistent structure (idx recomputed per iteration, block-uniform
// og bands, no sync in the loop), with OB=2 so the static per-SM makespan
// imbalance drops from ~3.6% (4-vs-3 iters) to ~1.2% (7-vs-6 iters).
// ---------------------------------------------------------------------------
#define MAIN_BLOCKS 592     // 148 SMs * 4 resident blocks
#define MAIN_THREADS 256

__global__ void __launch_bounds__(MAIN_THREADS)
main_kernel(const float4* __restrict__ tW,
            const float4* __restrict__ nW,
            float4* __restrict__ outW)
{
    cudaGridDependencySynchronize();

    const int total = (O_ / OB) * I4_;   // 1048576 tiles
    for (int idx = blockIdx.x * MAIN_THREADS + threadIdx.x;
         idx < total;
         idx += MAIN_BLOCKS * MAIN_THREADS) {

        const int i4 = idx & (I4_ - 1);
        const int o0 = (idx >> 10) * OB;

        const float4 a = g_a4[i4];
        float4 acc[OB];
        #pragma unroll
        for (int oo = 0; oo < OB; oo++) {
            const float4 t = __ldcs(&tW[(size_t)(o0 + oo) * I4_ + i4]);
            acc[oo].x = t.x * a.x;
            acc[oo].y = t.y * a.y;
            acc[oo].z = t.z * a.z;
            acc[oo].w = t.w * a.w;
        }

        #pragma unroll 4
        for (int n = 0; n < N_; n++) {
            const float4 wv = g_wnm4[n * I4_ + i4];          // L1/L2-resident
            const size_t base = (size_t)n * (O_ * I4_);
            #pragma unroll
            for (int oo = 0; oo < OB; oo++) {
                const float4 Wv = __ldcs(&nW[base + (size_t)(o0 + oo) * I4_ + i4]);
                acc[oo].x += wv.x * Wv.x;
                acc[oo].y += wv.y * Wv.y;
                acc[oo].z += wv.z * Wv.z;
                acc[oo].w += wv.w * Wv.w;
            }
        }

        #pragma unroll
        for (int oo = 0; oo < OB; oo++)
            __stcs(&outW[(size_t)(o0 + oo) * I4_ + i4], acc[oo]);
    }
}

// ---------------------------------------------------------------------------
extern "C" void kernel_launch(void* const* d_in, const int* in_sizes, int n_in,
                              void* d_out, int out_size)
{
    const float* edge_feats     = (const float*)d_in[0];
    const float* node_feats     = (const float*)d_in[1];
    const float* W1e            = (const float*)d_in[2];
    const float* b1e            = (const float*)d_in[3];
    const float* W2e            = (const float*)d_in[4];
    const float* b2e            = (const float*)d_in[5];
    const float* W1n            = (const float*)d_in[6];
    const float* b1n            = (const float*)d_in[7];
    const float* W2n            = (const float*)d_in[8];
    const float* b2n            = (const float*)d_in[9];
    const float* target_W       = (const float*)d_in[10];
    const float* neighbor_W     = (const float*)d_in[11];
    const float* target_b       = (const float*)d_in[12];
    const float* neighbor_b     = (const float*)d_in[13];
    const int*   target_mask    = (const int*)d_in[14];
    const int*   neighbor_masks = (const int*)d_in[15];

    float* out   = (float*)d_out;
    float* out_b = out + (size_t)O_ * I_;

    prologue_kernel<<<I_ / 128, 128>>>(edge_feats, node_feats,
                                       W1e, b1e, W2e, b2e,
                                       W1n, b1n, W2n, b2n,
                                       target_b, neighbor_b,
                                       target_mask, neighbor_masks,
                                       out_b);

    // PDL: main blocks scheduled while the prologue runs; gridDepSync inside
    // gates reads of g_a4/g_wnm4.
    {
        cudaLaunchConfig_t cfg = {};
        cfg.gridDim  = dim3(MAIN_BLOCKS, 1, 1);
        cfg.blockDim = dim3(MAIN_THREADS, 1, 1);
        cfg.dynamicSmemBytes = 0;
        cfg.stream = 0;

        cudaLaunchAttribute attrs[1];
        attrs[0].id = cudaLaunchAttributeProgrammaticStreamSerialization;
        attrs[0].val.programmaticStreamSerializationAllowed = 1;
        cfg.attrs = attrs;
        cfg.numAttrs = 1;

        cudaLaunchKernelEx(&cfg, main_kernel,
                           (const float4*)target_W,
                           (const float4*)neighbor_W,
                           (float4*)out);
    }
}